// round 5
// baseline (speedup 1.0000x reference)
#include <cuda_runtime.h>
#include <cstdint>

#define D_DIM 64
#define BT 64            // b per block
#define NT 64            // n per block
#define TPB 256
#define XSTRIDE 68       // floats; 16B-aligned row stride, conflict-free
#define ASTRIDE 68
#define AROWS (D_DIM + 1)   // +1 pad row: pipeline prefetches d=64 harmlessly

// ---- packed f32x2 helpers (Blackwell FFMA2 path) ----
__device__ __forceinline__ uint64_t pk2(float lo, float hi) {
    uint64_t r; asm("mov.b64 %0, {%1, %2};" : "=l"(r) : "f"(lo), "f"(hi)); return r;
}
__device__ __forceinline__ void upk2(uint64_t v, float& lo, float& hi) {
    asm("mov.b64 {%0, %1}, %2;" : "=f"(lo), "=f"(hi) : "l"(v));
}
__device__ __forceinline__ uint64_t fma2(uint64_t a, uint64_t b, uint64_t c) {
    uint64_t d; asm("fma.rn.f32x2 %0, %1, %2, %3;" : "=l"(d) : "l"(a), "l"(b), "l"(c)); return d;
}
__device__ __forceinline__ uint64_t mul2(uint64_t a, uint64_t b) {
    uint64_t d; asm("mul.rn.f32x2 %0, %1, %2;" : "=l"(d) : "l"(a), "l"(b)); return d;
}
__device__ __forceinline__ uint64_t add2(uint64_t a, uint64_t b) {
    uint64_t d; asm("add.rn.f32x2 %0, %1, %2;" : "=l"(d) : "l"(a), "l"(b)); return d;
}

extern __shared__ float smem_dyn[];

__device__ __forceinline__ void ldab(const float* __restrict__ arow,
                                     const float* __restrict__ brow,
                                     int d, uint64_t (&A)[2], uint64_t (&B)[2])
{
    const ulonglong2 av = *reinterpret_cast<const ulonglong2*>(arow + d * ASTRIDE);
    const ulonglong2 bv = *reinterpret_cast<const ulonglong2*>(brow + d * ASTRIDE);
    A[0] = av.x; A[1] = av.y;
    B[0] = bv.x; B[1] = bv.y;
}

__global__ __launch_bounds__(TPB, 2)
void wavelet_kernel(const float* __restrict__ x,
                    const float* __restrict__ centers,
                    const float* __restrict__ scales,
                    float* __restrict__ out, int N)
{
    float* sx = smem_dyn;                     // [BT][XSTRIDE]   b-major
    float* sa = sx + BT * XSTRIDE;            // [AROWS][ASTRIDE] d-major: 1/s
    float* sb = sa + AROWS * ASTRIDE;         // [AROWS][ASTRIDE] -c/s

    const int tid = threadIdx.x;
    const int b0 = blockIdx.x * BT;
    const int n0 = blockIdx.y * NT;

    // x tile (coalesced)
    #pragma unroll 2
    for (int i = tid; i < BT * D_DIM; i += TPB) {
        int r = i >> 6, c = i & 63;
        sx[r * XSTRIDE + c] = x[(b0 + r) * D_DIM + c];
    }
    // a/b tiles, transposed to [d][n]
    #pragma unroll 4
    for (int i = tid; i < NT * D_DIM; i += TPB) {
        int d = i & 63, n = i >> 6;
        int g = (n0 + n) * D_DIM + d;
        float inv = 1.0f / scales[g];
        sa[d * ASTRIDE + n] = inv;
        sb[d * ASTRIDE + n] = -centers[g] * inv;
    }
    __syncthreads();

    const int ng = tid & 15;   // 4 n's at ng*4 (2 packed pairs)
    const int bg = tid >> 4;   // 4 b's at bg*4

    const float* xrow = sx + (bg * 4) * XSTRIDE;
    const float* arow = sa + ng * 4;
    const float* brow = sb + ng * 4;

    const uint64_t M1 = pk2(-1.0f, -1.0f);
    uint64_t sacc[4][2], pacc[4][2];
    #pragma unroll
    for (int bi = 0; bi < 4; bi++)
        #pragma unroll
        for (int k = 0; k < 2; k++) { sacc[bi][k] = pk2(0.f, 0.f); pacc[bi][k] = pk2(1.f, 1.f); }

    // ---- pipeline prologue: stage x for dblk 0 and a/b for d=0 ----
    float4 xc[4], xn[4];
    #pragma unroll
    for (int bi = 0; bi < 4; bi++)
        xc[bi] = *reinterpret_cast<const float4*>(xrow + bi * XSTRIDE);

    uint64_t Ac[2], Bc[2];
    ldab(arow, brow, 0, Ac, Bc);

    #pragma unroll 1
    for (int dblk = 0; dblk < D_DIM; dblk += 4) {
        #pragma unroll
        for (int dd = 0; dd < 4; dd++) {
            // prefetch next d's a/b (d = dblk+dd+1; row 64 is a pad row)
            uint64_t An[2], Bn[2];
            ldab(arow, brow, dblk + dd + 1, An, Bn);
            // prefetch next dblk's x, one row per dd (col 64..67 = row padding)
            xn[dd] = *reinterpret_cast<const float4*>(xrow + dd * XSTRIDE + dblk + 4);

            // compute burst: 4 b x 2 pairs with current Ac/Bc
            const float* xf = reinterpret_cast<const float*>(xc);
            #pragma unroll
            for (int bi = 0; bi < 4; bi++) {
                const float xs = xf[bi * 4 + dd];
                const uint64_t xp = pk2(xs, xs);
                #pragma unroll
                for (int k = 0; k < 2; k++) {
                    uint64_t z = fma2(xp, Ac[k], Bc[k]);
                    uint64_t w = fma2(z, z, M1);          // z^2 - 1
                    sacc[bi][k] = add2(sacc[bi][k], w);
                    pacc[bi][k] = mul2(pacc[bi][k], w);
                }
            }
            Ac[0] = An[0]; Ac[1] = An[1];
            Bc[0] = Bn[0]; Bc[1] = Bn[1];
        }
        #pragma unroll
        for (int bi = 0; bi < 4; bi++) xc[bi] = xn[bi];

        // range-control fold after first 32 dims (|prod of (z^2-1)| can blow up)
        if (dblk == 28) {
            #pragma unroll
            for (int bi = 0; bi < 4; bi++)
                #pragma unroll
                for (int k = 0; k < 2; k++) {
                    float s0, s1, p0, p1;
                    upk2(sacc[bi][k], s0, s1);
                    upk2(pacc[bi][k], p0, p1);
                    p0 *= __expf(-0.5f * (s0 + 32.0f));
                    p1 *= __expf(-0.5f * (s1 + 32.0f));
                    pacc[bi][k] = pk2(p0, p1);
                    sacc[bi][k] = pk2(0.f, 0.f);
                }
        }
    }

    // epilogue
    float* orow = out + (long)(b0 + bg * 4) * N + n0 + ng * 4;
    #pragma unroll
    for (int bi = 0; bi < 4; bi++) {
        float h[4];
        #pragma unroll
        for (int k = 0; k < 2; k++) {
            float s0, s1, p0, p1;
            upk2(sacc[bi][k], s0, s1);
            upk2(pacc[bi][k], p0, p1);
            h[2 * k]     = p0 * __expf(-0.5f * (s0 + 32.0f));
            h[2 * k + 1] = p1 * __expf(-0.5f * (s1 + 32.0f));
        }
        float4 v = {h[0], h[1], h[2], h[3]};
        *reinterpret_cast<float4*>(orow + (long)bi * N) = v;
    }
}

extern "C" void kernel_launch(void* const* d_in, const int* in_sizes, int n_in,
                              void* d_out, int out_size)
{
    const float* x       = (const float*)d_in[0];
    const float* centers = (const float*)d_in[1];
    const float* scales  = (const float*)d_in[2];
    float* out = (float*)d_out;

    const int B = in_sizes[0] / D_DIM;   // 8192
    const int N = in_sizes[1] / D_DIM;   // 512

    const int smem_bytes = (BT * XSTRIDE + 2 * AROWS * ASTRIDE) * sizeof(float); // 52768
    static bool attr_set = false;
    if (!attr_set) {
        cudaFuncSetAttribute(wavelet_kernel,
                             cudaFuncAttributeMaxDynamicSharedMemorySize, smem_bytes);
        attr_set = true;
    }

    dim3 grid(B / BT, N / NT);           // (128, 8) = 1024 blocks
    wavelet_kernel<<<grid, TPB, smem_bytes>>>(x, centers, scales, out, N);
}